// round 16
// baseline (speedup 1.0000x reference)
#include <cuda_runtime.h>
#include <math.h>
#include <stdint.h>

// Problem constants
constexpr int kN  = 32768;
constexpr int kC  = 512;
constexpr int kC3 = 1536;
constexpr int kH  = 8;
constexpr int kD  = 64;
constexpr int kW  = 256;
constexpr int kNW = kN / kW;   // 128 windows
constexpr int kSHIFT = 128;
constexpr float kSCALE = 0.125f;  // 1/sqrt(64)

// Scratch (static device arrays — no allocation at runtime)
__device__ float g_qkv[(size_t)kN * kC3];   // 192 MB
__device__ float g_h[(size_t)kN * kC];      // attention output (tf32-rounded)
__device__ float g_xr[(size_t)kN * kC];     // x, tf32-rounded
__device__ float g_Wqkv_r[(size_t)kC * kC3];
__device__ float g_Wout_r[(size_t)kC * kC];

__device__ __forceinline__ uint32_t f2tf32(float x) {
    uint32_t r;
    asm("cvt.rna.tf32.f32 %0, %1;" : "=r"(r) : "f"(x));
    return r;
}

__device__ __forceinline__ void mma_tf32(
    float& c0, float& c1, float& c2, float& c3,
    uint32_t a0, uint32_t a1, uint32_t a2, uint32_t a3,
    uint32_t b0, uint32_t b1)
{
    asm volatile(
        "mma.sync.aligned.m16n8k8.row.col.f32.tf32.tf32.f32 "
        "{%0,%1,%2,%3}, {%4,%5,%6,%7}, {%8,%9}, {%0,%1,%2,%3};"
        : "+f"(c0), "+f"(c1), "+f"(c2), "+f"(c3)
        : "r"(a0), "r"(a1), "r"(a2), "r"(a3), "r"(b0), "r"(b1));
}

// ---------------------------------------------------------------------------
// Elementwise tf32-rounding pass: dst[i] = rna_tf32(src[i]). n % 4 == 0.
// ---------------------------------------------------------------------------
__global__ void __launch_bounds__(256) round_tf32_kernel(
    const float* __restrict__ src, float* __restrict__ dst, int n4)
{
    int i = blockIdx.x * blockDim.x + threadIdx.x;
    if (i < n4) {
        float4 v = ((const float4*)src)[i];
        float4 o;
        o.x = __uint_as_float(f2tf32(v.x));
        o.y = __uint_as_float(f2tf32(v.y));
        o.z = __uint_as_float(f2tf32(v.z));
        o.w = __uint_as_float(f2tf32(v.w));
        ((float4*)dst)[i] = o;
    }
}

// ---------------------------------------------------------------------------
// tf32 tensor-core GEMM with bias, inputs PRE-ROUNDED to tf32 bit patterns.
// BK=32: 4 k-steps (64 MMAs/warp) per barrier period — halves the per-
// iteration sync/wait overhead that was capping tensor% at 42.
// C[M,Nn] = A[M,K] @ B[K,Nn] + bias[Nn].  BM=BN=128, 8 warps, 2 CTAs/SM.
// ---------------------------------------------------------------------------
__global__ void __launch_bounds__(256, 2) gemm_tf32_bias(
    const float* __restrict__ A, const float* __restrict__ B,
    const float* __restrict__ bias, float* __restrict__ C,
    int M, int Nn, int K)
{
    constexpr int BM = 128, BN = 128, BK = 32;
    constexpr int ASTR = BK + 4;    // 36: banks (4*gr+tq) distinct
    constexpr int BSTR = BN + 8;    // 136: banks (8*tq+gr) distinct

    __shared__ float As[2][BM * ASTR];   // 2 * 18 KB
    __shared__ float Bs[2][BK * BSTR];   // 2 * 17 KB

    const int tid  = threadIdx.x;
    const int m0   = blockIdx.y * BM;
    const int n0   = blockIdx.x * BN;
    const int lane = tid & 31;
    const int warp = tid >> 5;
    const int wm   = (warp & 1) * 64;
    const int wn   = (warp >> 1) * 32;
    const int gr   = lane >> 2;
    const int tq   = lane & 3;

    float acc[4][4][4] = {};

    auto loadTiles = [&](int stage, int k0) {
        // A tile: 128x32 = 1024 float4 chunks, 4 per thread
#pragma unroll
        for (int u = 0; u < 4; u++) {
            int c = u * 256 + tid;
            int r = c >> 3, kc = (c & 7) * 4;
            uint32_t dst = (uint32_t)__cvta_generic_to_shared(&As[stage][r * ASTR + kc]);
            const float* src = A + (size_t)(m0 + r) * K + k0 + kc;
            asm volatile("cp.async.cg.shared.global [%0], [%1], 16;\n" :: "r"(dst), "l"(src));
        }
        // B tile: 32x128 = 1024 float4 chunks, 4 per thread
#pragma unroll
        for (int u = 0; u < 4; u++) {
            int c = u * 256 + tid;
            int r = c >> 5, nc = (c & 31) * 4;
            uint32_t dst = (uint32_t)__cvta_generic_to_shared(&Bs[stage][r * BSTR + nc]);
            const float* src = B + (size_t)(k0 + r) * Nn + n0 + nc;
            asm volatile("cp.async.cg.shared.global [%0], [%1], 16;\n" :: "r"(dst), "l"(src));
        }
    };

    const int nit = K / BK;   // 16
    loadTiles(0, 0);
    asm volatile("cp.async.commit_group;\n" ::: "memory");

    for (int it = 0; it < nit; ++it) {
        if (it + 1 < nit) loadTiles((it + 1) & 1, (it + 1) * BK);
        asm volatile("cp.async.commit_group;\n" ::: "memory");
        asm volatile("cp.async.wait_group 1;\n" ::: "memory");
        __syncthreads();

        const float* as = As[it & 1];
        const float* bs = Bs[it & 1];

#pragma unroll
        for (int ks = 0; ks < 4; ++ks) {
            const int k = ks * 8;
            uint32_t af[4][4], bf[4][2];
#pragma unroll
            for (int im = 0; im < 4; im++) {
                const int mb = wm + im * 16;
                af[im][0] = __float_as_uint(as[(mb + gr)     * ASTR + k + tq]);
                af[im][1] = __float_as_uint(as[(mb + gr + 8) * ASTR + k + tq]);
                af[im][2] = __float_as_uint(as[(mb + gr)     * ASTR + k + tq + 4]);
                af[im][3] = __float_as_uint(as[(mb + gr + 8) * ASTR + k + tq + 4]);
            }
#pragma unroll
            for (int jn = 0; jn < 4; jn++) {
                const int nb = wn + jn * 8;
                bf[jn][0] = __float_as_uint(bs[(k + tq)     * BSTR + nb + gr]);
                bf[jn][1] = __float_as_uint(bs[(k + tq + 4) * BSTR + nb + gr]);
            }
#pragma unroll
            for (int im = 0; im < 4; im++)
#pragma unroll
                for (int jn = 0; jn < 4; jn++)
                    mma_tf32(acc[im][jn][0], acc[im][jn][1], acc[im][jn][2], acc[im][jn][3],
                             af[im][0], af[im][1], af[im][2], af[im][3],
                             bf[jn][0], bf[jn][1]);
        }
        __syncthreads();
    }

#pragma unroll
    for (int im = 0; im < 4; im++) {
        const int mrow = m0 + wm + im * 16 + gr;
#pragma unroll
        for (int jn = 0; jn < 4; jn++) {
            const int ncol = n0 + wn + jn * 8 + 2 * tq;
            const float b0v = bias[ncol], b1v = bias[ncol + 1];
            float2 o0 = make_float2(acc[im][jn][0] + b0v, acc[im][jn][1] + b1v);
            float2 o1 = make_float2(acc[im][jn][2] + b0v, acc[im][jn][3] + b1v);
            *(float2*)&C[(size_t)mrow       * Nn + ncol] = o0;
            *(float2*)&C[(size_t)(mrow + 8) * Nn + ncol] = o1;
        }
    }
}

// ---------------------------------------------------------------------------
// Fused windowed attention with inline RoPE+RMS+roll (validated).
// Stores h pre-rounded to tf32 so GEMM2's inner loop stays CVT-free.
// ---------------------------------------------------------------------------
constexpr int KSTR = 68;
constexpr int SSTR = 260;
constexpr int kAttnSmemFloats = kW * KSTR + kD * SSTR + 64 * SSTR + 64 * KSTR + 64;

__global__ void __launch_bounds__(256, 1) attn_tc_kernel(
    const float* __restrict__ qkv, const int* __restrict__ coords,
    const float* __restrict__ gamma_q, const float* __restrict__ gamma_k,
    float* __restrict__ gh)
{
    extern __shared__ float smem[];
    float* Ks = smem;
    float* VT = Ks + kW * KSTR;
    float* Ss = VT + kD * SSTR;
    float* Qs = Ss + 64 * SSTR;
    float* rs = Qs + 64 * KSTR;

    const int w   = blockIdx.x;
    const int h   = blockIdx.y;
    const int tid = threadIdx.x;
    const int lane = tid & 31;
    const int warp = tid >> 5;
    const int gr = lane >> 2;
    const int tq = lane & 3;
    const unsigned FULL = 0xffffffffu;

    const int  cidx  = (lane < 30) ? (lane / 10) : 0;
    const bool hasth = (lane < 30);
    const float freq = hasth ? __powf(10000.0f, -(float)(lane % 10) * 0.1f) : 0.0f;
    const float2 gk2 = *(const float2*)&gamma_k[h * kD + 2 * lane];
    const float2 gq2 = *(const float2*)&gamma_q[h * kD + 2 * lane];

    const int krow_l   = warp * 32 + lane;
    const int ktoken_l = (w * kW + krow_l + kSHIFT) & (kN - 1);
    const int kc0 = __ldg(&coords[ktoken_l * 3 + 0]);
    const int kc1 = __ldg(&coords[ktoken_l * 3 + 1]);
    const int kc2 = __ldg(&coords[ktoken_l * 3 + 2]);
    const int qrow_l   = (lane >> 3) * 64 + warp * 8 + (lane & 7);
    const int qtoken_l = (w * kW + qrow_l + kSHIFT) & (kN - 1);
    const int qc0 = __ldg(&coords[qtoken_l * 3 + 0]);
    const int qc1 = __ldg(&coords[qtoken_l * 3 + 1]);
    const int qc2 = __ldg(&coords[qtoken_l * 3 + 2]);

    for (int g = 0; g < 8; g++) {
        float2 kd[4], vd[4];
#pragma unroll
        for (int u = 0; u < 4; u++) {
            const int r = warp * 32 + g * 4 + u;
            const int token = (w * kW + r + kSHIFT) & (kN - 1);
            const float* base = qkv + (size_t)token * kC3 + h * kD + 2 * lane;
            kd[u] = *(const float2*)&base[kC];
            vd[u] = *(const float2*)&base[2 * kC];
        }
#pragma unroll
        for (int u = 0; u < 4; u++) {
            const int r = warp * 32 + g * 4 + u;
            const int ridx = g * 4 + u;
            const float c0 = (float)__shfl_sync(FULL, kc0, ridx);
            const float c1 = (float)__shfl_sync(FULL, kc1, ridx);
            const float c2 = (float)__shfl_sync(FULL, kc2, ridx);
            const float coord = (cidx == 0) ? c0 : ((cidx == 1) ? c1 : c2);
            const float th = hasth ? coord * freq : 0.0f;
            float s, c;
            __sincosf(th, &s, &c);

            float kr0 = kd[u].x * c - kd[u].y * s;
            float kr1 = kd[u].x * s + kd[u].y * c;
            float sq = kr0 * kr0 + kr1 * kr1;
#pragma unroll
            for (int off = 16; off > 0; off >>= 1)
                sq += __shfl_xor_sync(FULL, sq, off);
            float inv = 8.0f * rsqrtf(sq + 1e-12f);
            *(float2*)&Ks[r * KSTR + 2 * lane] =
                make_float2(kr0 * inv * gk2.x, kr1 * inv * gk2.y);

            VT[(2 * lane + 0) * SSTR + r] = vd[u].x;
            VT[(2 * lane + 1) * SSTR + r] = vd[u].y;
        }
    }

    for (int qb = 0; qb < 4; qb++) {
        __syncthreads();
        for (int g = 0; g < 2; g++) {
            float2 qd[4];
#pragma unroll
            for (int u = 0; u < 4; u++) {
                const int rl = warp * 8 + g * 4 + u;
                const int token = (w * kW + qb * 64 + rl + kSHIFT) & (kN - 1);
                const float* base = qkv + (size_t)token * kC3 + h * kD + 2 * lane;
                qd[u] = *(const float2*)base;
            }
#pragma unroll
            for (int u = 0; u < 4; u++) {
                const int rl = warp * 8 + g * 4 + u;
                const int ridx = qb * 8 + g * 4 + u;
                const float c0 = (float)__shfl_sync(FULL, qc0, ridx);
                const float c1 = (float)__shfl_sync(FULL, qc1, ridx);
                const float c2 = (float)__shfl_sync(FULL, qc2, ridx);
                const float coord = (cidx == 0) ? c0 : ((cidx == 1) ? c1 : c2);
                const float th = hasth ? coord * freq : 0.0f;
                float s, c;
                __sincosf(th, &s, &c);

                float qr0 = qd[u].x * c - qd[u].y * s;
                float qr1 = qd[u].x * s + qd[u].y * c;
                float sq = qr0 * qr0 + qr1 * qr1;
#pragma unroll
                for (int off = 16; off > 0; off >>= 1)
                    sq += __shfl_xor_sync(FULL, sq, off);
                float inv = 8.0f * rsqrtf(sq + 1e-12f);
                *(float2*)&Qs[rl * KSTR + 2 * lane] =
                    make_float2(qr0 * inv * gq2.x, qr1 * inv * gq2.y);
            }
        }
        __syncthreads();

        {
            const int wn = warp * 32;
            float acc[4][4][4] = {};
#pragma unroll
            for (int ks = 0; ks < 8; ks++) {
                const int k = ks * 8;
                uint32_t af[4][4], bf[4][2];
#pragma unroll
                for (int im = 0; im < 4; im++) {
                    const int mb = im * 16;
                    af[im][0] = f2tf32(Qs[(mb + gr)     * KSTR + k + tq]);
                    af[im][1] = f2tf32(Qs[(mb + gr + 8) * KSTR + k + tq]);
                    af[im][2] = f2tf32(Qs[(mb + gr)     * KSTR + k + tq + 4]);
                    af[im][3] = f2tf32(Qs[(mb + gr + 8) * KSTR + k + tq + 4]);
                }
#pragma unroll
                for (int jn = 0; jn < 4; jn++) {
                    const int nb = wn + jn * 8;
                    bf[jn][0] = f2tf32(Ks[(nb + gr) * KSTR + k + tq]);
                    bf[jn][1] = f2tf32(Ks[(nb + gr) * KSTR + k + tq + 4]);
                }
#pragma unroll
                for (int im = 0; im < 4; im++)
#pragma unroll
                    for (int jn = 0; jn < 4; jn++)
                        mma_tf32(acc[im][jn][0], acc[im][jn][1], acc[im][jn][2], acc[im][jn][3],
                                 af[im][0], af[im][1], af[im][2], af[im][3],
                                 bf[jn][0], bf[jn][1]);
            }
#pragma unroll
            for (int im = 0; im < 4; im++) {
                const int r0 = im * 16 + gr;
#pragma unroll
                for (int jn = 0; jn < 4; jn++) {
                    const int c = wn + jn * 8 + 2 * tq;
                    *(float2*)&Ss[r0 * SSTR + c] =
                        make_float2(acc[im][jn][0] * kSCALE, acc[im][jn][1] * kSCALE);
                    *(float2*)&Ss[(r0 + 8) * SSTR + c] =
                        make_float2(acc[im][jn][2] * kSCALE, acc[im][jn][3] * kSCALE);
                }
            }
        }
        __syncthreads();

        for (int rr = 0; rr < 8; rr++) {
            const int r = warp * 8 + rr;
            float v[8];
            float m = -1e30f;
#pragma unroll
            for (int i = 0; i < 8; i++) {
                v[i] = Ss[r * SSTR + lane + 32 * i];
                m = fmaxf(m, v[i]);
            }
#pragma unroll
            for (int off = 16; off > 0; off >>= 1)
                m = fmaxf(m, __shfl_xor_sync(FULL, m, off));
            float sum = 0.0f;
#pragma unroll
            for (int i = 0; i < 8; i++) {
                v[i] = __expf(v[i] - m);
                sum += v[i];
                Ss[r * SSTR + lane + 32 * i] = v[i];
            }
#pragma unroll
            for (int off = 16; off > 0; off >>= 1)
                sum += __shfl_xor_sync(FULL, sum, off);
            if (lane == 0) rs[r] = sum;
        }
        __syncthreads();

        {
            const int wm  = (warp >> 1) * 16;
            const int wn2 = (warp & 1) * 32;
            float acc[4][4] = {};
#pragma unroll
            for (int ks = 0; ks < 32; ks++) {
                const int k = ks * 8;
                uint32_t af[4], bf[4][2];
                af[0] = f2tf32(Ss[(wm + gr)     * SSTR + k + tq]);
                af[1] = f2tf32(Ss[(wm + gr + 8) * SSTR + k + tq]);
                af[2] = f2tf32(Ss[(wm + gr)     * SSTR + k + tq + 4]);
                af[3] = f2tf32(Ss[(wm + gr + 8) * SSTR + k + tq + 4]);
#pragma unroll
                for (int jn = 0; jn < 4; jn++) {
                    const int nb = wn2 + jn * 8;
                    bf[jn][0] = f2tf32(VT[(nb + gr) * SSTR + k + tq]);
                    bf[jn][1] = f2tf32(VT[(nb + gr) * SSTR + k + tq + 4]);
                }
#pragma unroll
                for (int jn = 0; jn < 4; jn++)
                    mma_tf32(acc[jn][0], acc[jn][1], acc[jn][2], acc[jn][3],
                             af[0], af[1], af[2], af[3], bf[jn][0], bf[jn][1]);
            }
            const float inv0 = 1.0f / rs[wm + gr];
            const float inv1 = 1.0f / rs[wm + gr + 8];
            const int q0 = w * kW + qb * 64 + wm + gr;
            const size_t io0 = (size_t)((q0 + kSHIFT) & (kN - 1));
            const size_t io1 = (size_t)((q0 + 8 + kSHIFT) & (kN - 1));
#pragma unroll
            for (int jn = 0; jn < 4; jn++) {
                const int c = h * kD + wn2 + jn * 8 + 2 * tq;
                *(float2*)&gh[io0 * kC + c] = make_float2(
                    __uint_as_float(f2tf32(acc[jn][0] * inv0)),
                    __uint_as_float(f2tf32(acc[jn][1] * inv0)));
                *(float2*)&gh[io1 * kC + c] = make_float2(
                    __uint_as_float(f2tf32(acc[jn][2] * inv1)),
                    __uint_as_float(f2tf32(acc[jn][3] * inv1)));
            }
        }
    }
}

// ---------------------------------------------------------------------------
extern "C" void kernel_launch(void* const* d_in, const int* in_sizes, int n_in,
                              void* d_out, int out_size)
{
    const float* x      = (const float*)d_in[0];
    const int*   coords = (const int*)  d_in[1];
    const float* Wqkv   = (const float*)d_in[2];
    const float* b_qkv  = (const float*)d_in[3];
    const float* gamq   = (const float*)d_in[4];
    const float* gamk   = (const float*)d_in[5];
    const float* Wout   = (const float*)d_in[6];
    const float* b_out  = (const float*)d_in[7];
    float* out = (float*)d_out;

    float *pqkv, *ph, *pxr, *pWqkv_r, *pWout_r;
    cudaGetSymbolAddress((void**)&pqkv,    g_qkv);
    cudaGetSymbolAddress((void**)&ph,      g_h);
    cudaGetSymbolAddress((void**)&pxr,     g_xr);
    cudaGetSymbolAddress((void**)&pWqkv_r, g_Wqkv_r);
    cudaGetSymbolAddress((void**)&pWout_r, g_Wout_r);

    // 0) pre-round GEMM inputs to tf32 bit patterns (rna)
    {
        int n4x = kN * kC / 4;
        round_tf32_kernel<<<(n4x + 255) / 256, 256>>>(x, pxr, n4x);
        int n4w = kC * kC3 / 4;
        round_tf32_kernel<<<(n4w + 255) / 256, 256>>>(Wqkv, pWqkv_r, n4w);
        int n4o = kC * kC / 4;
        round_tf32_kernel<<<(n4o + 255) / 256, 256>>>(Wout, pWout_r, n4o);
    }

    // 1) qkv = x @ Wqkv + b_qkv   (tf32 MMA, BK=32)
    gemm_tf32_bias<<<dim3(kC3 / 128, kN / 128), 256>>>(pxr, pWqkv_r, b_qkv, pqkv, kN, kC3, kC);

    // 2) fused RoPE+RMS+roll + windowed attention
    static const int kAttnSmem = kAttnSmemFloats * (int)sizeof(float);
    cudaFuncSetAttribute(attn_tc_kernel, cudaFuncAttributeMaxDynamicSharedMemorySize, kAttnSmem);
    attn_tc_kernel<<<dim3(kNW, kH), 256, kAttnSmem>>>(pqkv, coords, gamq, gamk, ph);

    // 3) out = h @ Wout + b_out   (tf32 MMA, BK=32)
    gemm_tf32_bias<<<dim3(kC / 128, kN / 128), 256>>>(ph, pWout_r, b_out, out, kN, kC, kC);
}

// round 17
// speedup vs baseline: 1.4699x; 1.4699x over previous
#include <cuda_runtime.h>
#include <math.h>
#include <stdint.h>

// Problem constants
constexpr int kN  = 32768;
constexpr int kC  = 512;
constexpr int kC3 = 1536;
constexpr int kH  = 8;
constexpr int kD  = 64;
constexpr int kW  = 256;
constexpr int kNW = kN / kW;   // 128 windows
constexpr int kSHIFT = 128;
constexpr float kSCALE = 0.125f;  // 1/sqrt(64)

// Scratch (static device arrays — no allocation at runtime)
__device__ float g_qkv[(size_t)kN * kC3];  // 192 MB
__device__ float g_h[(size_t)kN * kC];     // attention output, un-rolled frame

__device__ __forceinline__ uint32_t f2tf32(float x) {
    uint32_t r;
    asm("cvt.rna.tf32.f32 %0, %1;" : "=r"(r) : "f"(x));
    return r;
}

__device__ __forceinline__ void mma_tf32(
    float& c0, float& c1, float& c2, float& c3,
    uint32_t a0, uint32_t a1, uint32_t a2, uint32_t a3,
    uint32_t b0, uint32_t b1)
{
    asm volatile(
        "mma.sync.aligned.m16n8k8.row.col.f32.tf32.tf32.f32 "
        "{%0,%1,%2,%3}, {%4,%5,%6,%7}, {%8,%9}, {%0,%1,%2,%3};"
        : "+f"(c0), "+f"(c1), "+f"(c2), "+f"(c3)
        : "r"(a0), "r"(a1), "r"(a2), "r"(a3), "r"(b0), "r"(b1));
}

// ---------------------------------------------------------------------------
// tf32 tensor-core GEMM with bias (exact round-11 configuration — validated
// at 398/136 us): BM=BN=128, BK=16, cp.async double buffer, CVT in loop.
// ---------------------------------------------------------------------------
__global__ void __launch_bounds__(256, 2) gemm_tf32_bias(
    const float* __restrict__ A, const float* __restrict__ B,
    const float* __restrict__ bias, float* __restrict__ C,
    int M, int Nn, int K)
{
    constexpr int BM = 128, BN = 128, BK = 16;
    constexpr int ASTR = BK + 4;
    constexpr int BSTR = BN + 8;

    __shared__ float As[2][BM * ASTR];
    __shared__ float Bs[2][BK * BSTR];

    const int tid  = threadIdx.x;
    const int m0   = blockIdx.y * BM;
    const int n0   = blockIdx.x * BN;
    const int lane = tid & 31;
    const int warp = tid >> 5;
    const int wm   = (warp & 1) * 64;
    const int wn   = (warp >> 1) * 32;
    const int gr   = lane >> 2;
    const int tq   = lane & 3;

    float acc[4][4][4] = {};

    auto loadTiles = [&](int stage, int k0) {
#pragma unroll
        for (int u = 0; u < 2; u++) {
            int c = tid * 2 + u;
            int r = c >> 2, kc = (c & 3) * 4;
            uint32_t dst = (uint32_t)__cvta_generic_to_shared(&As[stage][r * ASTR + kc]);
            const float* src = A + (size_t)(m0 + r) * K + k0 + kc;
            asm volatile("cp.async.cg.shared.global [%0], [%1], 16;\n" :: "r"(dst), "l"(src));
        }
#pragma unroll
        for (int u = 0; u < 2; u++) {
            int c = tid * 2 + u;
            int r = c >> 5, nc = (c & 31) * 4;
            uint32_t dst = (uint32_t)__cvta_generic_to_shared(&Bs[stage][r * BSTR + nc]);
            const float* src = B + (size_t)(k0 + r) * Nn + n0 + nc;
            asm volatile("cp.async.cg.shared.global [%0], [%1], 16;\n" :: "r"(dst), "l"(src));
        }
    };

    const int nit = K / BK;
    loadTiles(0, 0);
    asm volatile("cp.async.commit_group;\n" ::: "memory");

    for (int it = 0; it < nit; ++it) {
        if (it + 1 < nit) loadTiles((it + 1) & 1, (it + 1) * BK);
        asm volatile("cp.async.commit_group;\n" ::: "memory");
        asm volatile("cp.async.wait_group 1;\n" ::: "memory");
        __syncthreads();

        const float* as = As[it & 1];
        const float* bs = Bs[it & 1];

#pragma unroll
        for (int ks = 0; ks < 2; ++ks) {
            const int k = ks * 8;
            uint32_t af[4][4], bf[4][2];
#pragma unroll
            for (int im = 0; im < 4; im++) {
                const int mb = wm + im * 16;
                af[im][0] = f2tf32(as[(mb + gr)     * ASTR + k + tq]);
                af[im][1] = f2tf32(as[(mb + gr + 8) * ASTR + k + tq]);
                af[im][2] = f2tf32(as[(mb + gr)     * ASTR + k + tq + 4]);
                af[im][3] = f2tf32(as[(mb + gr + 8) * ASTR + k + tq + 4]);
            }
#pragma unroll
            for (int jn = 0; jn < 4; jn++) {
                const int nb = wn + jn * 8;
                bf[jn][0] = f2tf32(bs[(k + tq)     * BSTR + nb + gr]);
                bf[jn][1] = f2tf32(bs[(k + tq + 4) * BSTR + nb + gr]);
            }
#pragma unroll
            for (int im = 0; im < 4; im++)
#pragma unroll
                for (int jn = 0; jn < 4; jn++)
                    mma_tf32(acc[im][jn][0], acc[im][jn][1], acc[im][jn][2], acc[im][jn][3],
                             af[im][0], af[im][1], af[im][2], af[im][3],
                             bf[jn][0], bf[jn][1]);
        }
        __syncthreads();
    }

#pragma unroll
    for (int im = 0; im < 4; im++) {
        const int mrow = m0 + wm + im * 16 + gr;
#pragma unroll
        for (int jn = 0; jn < 4; jn++) {
            const int ncol = n0 + wn + jn * 8 + 2 * tq;
            const float b0v = bias[ncol], b1v = bias[ncol + 1];
            float2 o0 = make_float2(acc[im][jn][0] + b0v, acc[im][jn][1] + b1v);
            float2 o1 = make_float2(acc[im][jn][2] + b0v, acc[im][jn][3] + b1v);
            *(float2*)&C[(size_t)mrow       * Nn + ncol] = o0;
            *(float2*)&C[(size_t)(mrow + 8) * Nn + ncol] = o1;
        }
    }
}

// ---------------------------------------------------------------------------
// Fused windowed attention with inline RoPE+RMS+roll — 512 threads / 16 warps
// per CTA (2x the warps of round 11 to hide gmem/LDS/MUFU latency; same smem,
// same math, same accumulation order).
// ---------------------------------------------------------------------------
constexpr int KSTR = 68;
constexpr int SSTR = 260;
constexpr int kAttnSmemFloats = kW * KSTR + kD * SSTR + 64 * SSTR + 64 * KSTR + 64;

__global__ void __launch_bounds__(512, 1) attn_tc_kernel(
    const float* __restrict__ qkv, const int* __restrict__ coords,
    const float* __restrict__ gamma_q, const float* __restrict__ gamma_k,
    float* __restrict__ gh)
{
    extern __shared__ float smem[];
    float* Ks = smem;                    // 256*68
    float* VT = Ks + kW * KSTR;          // 64*260
    float* Ss = VT + kD * SSTR;          // 64*260
    float* Qs = Ss + 64 * SSTR;          // 64*68
    float* rs = Qs + 64 * KSTR;          // 64 row sums

    const int w   = blockIdx.x;
    const int h   = blockIdx.y;
    const int tid = threadIdx.x;
    const int lane = tid & 31;
    const int warp = tid >> 5;           // 0..15
    const int gr = lane >> 2;
    const int tq = lane & 3;
    const unsigned FULL = 0xffffffffu;

    const int  cidx  = (lane < 30) ? (lane / 10) : 0;
    const bool hasth = (lane < 30);
    const float freq = hasth ? __powf(10000.0f, -(float)(lane % 10) * 0.1f) : 0.0f;
    const float2 gk2 = *(const float2*)&gamma_k[h * kD + 2 * lane];
    const float2 gq2 = *(const float2*)&gamma_q[h * kD + 2 * lane];

    // coords prefetch (lanes 0..15 hold live values; shfl reads only 0..15)
    // K side: lane l -> row warp*16 + l
    const int krow_l   = warp * 16 + lane;
    const int ktoken_l = (w * kW + krow_l + kSHIFT) & (kN - 1);
    const int kc0 = __ldg(&coords[ktoken_l * 3 + 0]);
    const int kc1 = __ldg(&coords[ktoken_l * 3 + 1]);
    const int kc2 = __ldg(&coords[ktoken_l * 3 + 2]);
    // Q side: lane l = qb*4+u -> local row qb*64 + warp*4 + u
    const int qrow_l   = (lane >> 2) * 64 + warp * 4 + (lane & 3);
    const int qtoken_l = (w * kW + qrow_l + kSHIFT) & (kN - 1);
    const int qc0 = __ldg(&coords[qtoken_l * 3 + 0]);
    const int qc1 = __ldg(&coords[qtoken_l * 3 + 1]);
    const int qc2 = __ldg(&coords[qtoken_l * 3 + 2]);

    // ---- K (rope+rms) + V^T: warp handles 16 rows, 4 groups of 4 (MLP=8) ----
    for (int g = 0; g < 4; g++) {
        float2 kd[4], vd[4];
#pragma unroll
        for (int u = 0; u < 4; u++) {
            const int r = warp * 16 + g * 4 + u;
            const int token = (w * kW + r + kSHIFT) & (kN - 1);
            const float* base = qkv + (size_t)token * kC3 + h * kD + 2 * lane;
            kd[u] = *(const float2*)&base[kC];
            vd[u] = *(const float2*)&base[2 * kC];
        }
#pragma unroll
        for (int u = 0; u < 4; u++) {
            const int r = warp * 16 + g * 4 + u;
            const int ridx = g * 4 + u;  // 0..15
            const float c0 = (float)__shfl_sync(FULL, kc0, ridx);
            const float c1 = (float)__shfl_sync(FULL, kc1, ridx);
            const float c2 = (float)__shfl_sync(FULL, kc2, ridx);
            const float coord = (cidx == 0) ? c0 : ((cidx == 1) ? c1 : c2);
            const float th = hasth ? coord * freq : 0.0f;
            float s, c;
            __sincosf(th, &s, &c);

            float kr0 = kd[u].x * c - kd[u].y * s;
            float kr1 = kd[u].x * s + kd[u].y * c;
            float sq = kr0 * kr0 + kr1 * kr1;
#pragma unroll
            for (int off = 16; off > 0; off >>= 1)
                sq += __shfl_xor_sync(FULL, sq, off);
            float inv = 8.0f * rsqrtf(sq + 1e-12f);
            *(float2*)&Ks[r * KSTR + 2 * lane] =
                make_float2(kr0 * inv * gk2.x, kr1 * inv * gk2.y);

            VT[(2 * lane + 0) * SSTR + r] = vd[u].x;
            VT[(2 * lane + 1) * SSTR + r] = vd[u].y;
        }
    }

    for (int qb = 0; qb < 4; qb++) {
        __syncthreads();
        // ---- Q block: warp handles 4 rows (one group, MLP=4) ----
        {
            float2 qd[4];
#pragma unroll
            for (int u = 0; u < 4; u++) {
                const int rl = warp * 4 + u;   // 0..63 local
                const int token = (w * kW + qb * 64 + rl + kSHIFT) & (kN - 1);
                const float* base = qkv + (size_t)token * kC3 + h * kD + 2 * lane;
                qd[u] = *(const float2*)base;
            }
#pragma unroll
            for (int u = 0; u < 4; u++) {
                const int rl = warp * 4 + u;
                const int ridx = qb * 4 + u;   // lane holding these coords
                const float c0 = (float)__shfl_sync(FULL, qc0, ridx);
                const float c1 = (float)__shfl_sync(FULL, qc1, ridx);
                const float c2 = (float)__shfl_sync(FULL, qc2, ridx);
                const float coord = (cidx == 0) ? c0 : ((cidx == 1) ? c1 : c2);
                const float th = hasth ? coord * freq : 0.0f;
                float s, c;
                __sincosf(th, &s, &c);

                float qr0 = qd[u].x * c - qd[u].y * s;
                float qr1 = qd[u].x * s + qd[u].y * c;
                float sq = qr0 * qr0 + qr1 * qr1;
#pragma unroll
                for (int off = 16; off > 0; off >>= 1)
                    sq += __shfl_xor_sync(FULL, sq, off);
                float inv = 8.0f * rsqrtf(sq + 1e-12f);
                *(float2*)&Qs[rl * KSTR + 2 * lane] =
                    make_float2(qr0 * inv * gq2.x, qr1 * inv * gq2.y);
            }
        }
        __syncthreads();

        // ---- phase 1: S = Q K^T; warp owns n-slice [warp*16, warp*16+16) ----
        {
            const int wn = warp * 16;
            float acc[4][2][4] = {};
#pragma unroll
            for (int ks = 0; ks < 8; ks++) {
                const int k = ks * 8;
                uint32_t af[4][4], bf[2][2];
#pragma unroll
                for (int im = 0; im < 4; im++) {
                    const int mb = im * 16;
                    af[im][0] = f2tf32(Qs[(mb + gr)     * KSTR + k + tq]);
                    af[im][1] = f2tf32(Qs[(mb + gr + 8) * KSTR + k + tq]);
                    af[im][2] = f2tf32(Qs[(mb + gr)     * KSTR + k + tq + 4]);
                    af[im][3] = f2tf32(Qs[(mb + gr + 8) * KSTR + k + tq + 4]);
                }
#pragma unroll
                for (int jn = 0; jn < 2; jn++) {
                    const int nb = wn + jn * 8;
                    bf[jn][0] = f2tf32(Ks[(nb + gr) * KSTR + k + tq]);
                    bf[jn][1] = f2tf32(Ks[(nb + gr) * KSTR + k + tq + 4]);
                }
#pragma unroll
                for (int im = 0; im < 4; im++)
#pragma unroll
                    for (int jn = 0; jn < 2; jn++)
                        mma_tf32(acc[im][jn][0], acc[im][jn][1], acc[im][jn][2], acc[im][jn][3],
                                 af[im][0], af[im][1], af[im][2], af[im][3],
                                 bf[jn][0], bf[jn][1]);
            }
#pragma unroll
            for (int im = 0; im < 4; im++) {
                const int r0 = im * 16 + gr;
#pragma unroll
                for (int jn = 0; jn < 2; jn++) {
                    const int c = wn + jn * 8 + 2 * tq;
                    *(float2*)&Ss[r0 * SSTR + c] =
                        make_float2(acc[im][jn][0] * kSCALE, acc[im][jn][1] * kSCALE);
                    *(float2*)&Ss[(r0 + 8) * SSTR + c] =
                        make_float2(acc[im][jn][2] * kSCALE, acc[im][jn][3] * kSCALE);
                }
            }
        }
        __syncthreads();

        // ---- phase 2: softmax; warp handles rows warp*4..warp*4+3 ----
        for (int rr = 0; rr < 4; rr++) {
            const int r = warp * 4 + rr;
            float v[8];
            float m = -1e30f;
#pragma unroll
            for (int i = 0; i < 8; i++) {
                v[i] = Ss[r * SSTR + lane + 32 * i];
                m = fmaxf(m, v[i]);
            }
#pragma unroll
            for (int off = 16; off > 0; off >>= 1)
                m = fmaxf(m, __shfl_xor_sync(FULL, m, off));
            float sum = 0.0f;
#pragma unroll
            for (int i = 0; i < 8; i++) {
                v[i] = __expf(v[i] - m);
                sum += v[i];
                Ss[r * SSTR + lane + 32 * i] = v[i];
            }
#pragma unroll
            for (int off = 16; off > 0; off >>= 1)
                sum += __shfl_xor_sync(FULL, sum, off);
            if (lane == 0) rs[r] = sum;
        }
        __syncthreads();

        // ---- phase 3: O = P V (M=64 N=64 K=256); warp tile 16x16 ----
        {
            const int wm  = (warp >> 2) * 16;
            const int wn2 = (warp & 3) * 16;
            float acc[2][4] = {};
#pragma unroll
            for (int ks = 0; ks < 32; ks++) {
                const int k = ks * 8;
                uint32_t af[4], bf[2][2];
                af[0] = f2tf32(Ss[(wm + gr)     * SSTR + k + tq]);
                af[1] = f2tf32(Ss[(wm + gr + 8) * SSTR + k + tq]);
                af[2] = f2tf32(Ss[(wm + gr)     * SSTR + k + tq + 4]);
                af[3] = f2tf32(Ss[(wm + gr + 8) * SSTR + k + tq + 4]);
#pragma unroll
                for (int jn = 0; jn < 2; jn++) {
                    const int nb = wn2 + jn * 8;
                    bf[jn][0] = f2tf32(VT[(nb + gr) * SSTR + k + tq]);
                    bf[jn][1] = f2tf32(VT[(nb + gr) * SSTR + k + tq + 4]);
                }
#pragma unroll
                for (int jn = 0; jn < 2; jn++)
                    mma_tf32(acc[jn][0], acc[jn][1], acc[jn][2], acc[jn][3],
                             af[0], af[1], af[2], af[3], bf[jn][0], bf[jn][1]);
            }
            const float inv0 = 1.0f / rs[wm + gr];
            const float inv1 = 1.0f / rs[wm + gr + 8];
            const int q0 = w * kW + qb * 64 + wm + gr;
            const size_t io0 = (size_t)((q0 + kSHIFT) & (kN - 1));
            const size_t io1 = (size_t)((q0 + 8 + kSHIFT) & (kN - 1));
#pragma unroll
            for (int jn = 0; jn < 2; jn++) {
                const int c = h * kD + wn2 + jn * 8 + 2 * tq;
                *(float2*)&gh[io0 * kC + c] =
                    make_float2(acc[jn][0] * inv0, acc[jn][1] * inv0);
                *(float2*)&gh[io1 * kC + c] =
                    make_float2(acc[jn][2] * inv1, acc[jn][3] * inv1);
            }
        }
    }
}

// ---------------------------------------------------------------------------
extern "C" void kernel_launch(void* const* d_in, const int* in_sizes, int n_in,
                              void* d_out, int out_size)
{
    const float* x      = (const float*)d_in[0];
    const int*   coords = (const int*)  d_in[1];
    const float* Wqkv   = (const float*)d_in[2];
    const float* b_qkv  = (const float*)d_in[3];
    const float* gamq   = (const float*)d_in[4];
    const float* gamk   = (const float*)d_in[5];
    const float* Wout   = (const float*)d_in[6];
    const float* b_out  = (const float*)d_in[7];
    float* out = (float*)d_out;

    float *pqkv, *ph;
    cudaGetSymbolAddress((void**)&pqkv, g_qkv);
    cudaGetSymbolAddress((void**)&ph,   g_h);

    // 1) qkv = x @ Wqkv + b_qkv   (tf32 MMA, round-11 config)
    gemm_tf32_bias<<<dim3(kC3 / 128, kN / 128), 256>>>(x, Wqkv, b_qkv, pqkv, kN, kC3, kC);

    // 2) fused RoPE+RMS+roll + windowed attention (512 threads)
    static const int kAttnSmem = kAttnSmemFloats * (int)sizeof(float);
    cudaFuncSetAttribute(attn_tc_kernel, cudaFuncAttributeMaxDynamicSharedMemorySize, kAttnSmem);
    attn_tc_kernel<<<dim3(kNW, kH), 512, kAttnSmem>>>(pqkv, coords, gamq, gamk, ph);

    // 3) out = h @ Wout + b_out   (tf32 MMA, round-11 config)
    gemm_tf32_bias<<<dim3(kC / 128, kN / 128), 256>>>(ph, Wout, b_out, out, kN, kC, kC);
}